// round 2
// baseline (speedup 1.0000x reference)
#include <cuda_runtime.h>

// DynamicUpsamplingFilter:
//   x:       (1, 3, 25, 128, 128) float32          -> d_in[0]
//   filters: (1, 25, 16, 25, 128, 128) float32     -> d_in[1]
//   out:     (1, 48, 25, 128, 128) float32
// out[c*16+u, t, h, w] = sum_{a,b} x[c, t, h+a-2, w+b-2] * filters[a*5+b, u, t, h, w]
//
// R2: split u 0..15 into two halves (blockIdx.y). 24 accumulators/thread
// -> ~48 regs -> ~10 CTAs/SM -> 2x warps in flight for DRAM latency hiding.
// Filters read with __ldcs (one-touch stream, evict-first).

#define T_DIM 25
#define H_DIM 128
#define W_DIM 128
#define HW    (H_DIM * W_DIM)       // 16384
#define THW   (T_DIM * HW)          // 409600
#define C_IN  3
#define KH    5
#define KW    5
#define NK    (KH * KW)             // 25
#define UPSQ  16
#define UHALF 8                     // u values per block

__global__ __launch_bounds__(W_DIM, 10)
void duf_kernel(const float* __restrict__ x,
                const float* __restrict__ f,
                float* __restrict__ out)
{
    const int w = threadIdx.x;           // 0..127
    const int h = blockIdx.x & (H_DIM - 1);
    const int t = blockIdx.x >> 7;
    const int u0 = blockIdx.y * UHALF;   // 0 or 8

    // x patch tile: 3 channels x 5 rows x (128 + 4) cols, zero halo in w
    __shared__ float sx[C_IN][KH][W_DIM + 4];

    if (w < 2) {
        #pragma unroll
        for (int c = 0; c < C_IN; c++)
            #pragma unroll
            for (int a = 0; a < KH; a++) {
                sx[c][a][w] = 0.0f;
                sx[c][a][W_DIM + 2 + w] = 0.0f;
            }
    }

    #pragma unroll
    for (int c = 0; c < C_IN; c++) {
        #pragma unroll
        for (int a = 0; a < KH; a++) {
            const int hh = h + a - 2;
            float v = 0.0f;
            if (hh >= 0 && hh < H_DIM)
                v = __ldg(&x[c * THW + t * HW + hh * W_DIM + w]);
            sx[c][a][w + 2] = v;
        }
    }
    __syncthreads();

    const int pix = t * HW + h * W_DIM + w;
    const float* fp = f + pix + (size_t)u0 * THW;

    float acc[C_IN * UHALF];
    #pragma unroll
    for (int i = 0; i < C_IN * UHALF; i++) acc[i] = 0.0f;

    // k outer (25 iters, kept rolled -> tiny I$ footprint),
    // u inner fully unrolled (8 independent streaming loads in flight)
    #pragma unroll 1
    for (int k = 0; k < NK; k++) {
        const int a = k / KW;
        const int b = k - a * KW;
        const float p0 = sx[0][a][w + b];
        const float p1 = sx[1][a][w + b];
        const float p2 = sx[2][a][w + b];
        const float* fk = fp + (size_t)k * (UPSQ * THW);
        #pragma unroll
        for (int u = 0; u < UHALF; u++) {
            const float fv = __ldcs(&fk[(size_t)u * THW]);
            acc[u]              = fmaf(p0, fv, acc[u]);
            acc[UHALF + u]      = fmaf(p1, fv, acc[UHALF + u]);
            acc[2 * UHALF + u]  = fmaf(p2, fv, acc[2 * UHALF + u]);
        }
    }

    // out[(c*16 + u0 + u)*THW + pix], coalesced across w
    #pragma unroll
    for (int c = 0; c < C_IN; c++)
        #pragma unroll
        for (int u = 0; u < UHALF; u++)
            out[(size_t)(c * UPSQ + u0 + u) * THW + pix] = acc[c * UHALF + u];
}

extern "C" void kernel_launch(void* const* d_in, const int* in_sizes, int n_in,
                              void* d_out, int out_size)
{
    const float* x = (const float*)d_in[0];
    const float* f = (const float*)d_in[1];
    float* out = (float*)d_out;

    dim3 grid(T_DIM * H_DIM, 2);  // (t*h rows, u-half)
    dim3 block(W_DIM);
    duf_kernel<<<grid, block>>>(x, f, out);
}

// round 3
// speedup vs baseline: 1.0676x; 1.0676x over previous
#include <cuda_runtime.h>

// DynamicUpsamplingFilter:
//   x:       (1, 3, 25, 128, 128) float32          -> d_in[0]
//   filters: (1, 25, 16, 25, 128, 128) float32     -> d_in[1]
//   out:     (1, 48, 25, 128, 128) float32
// out[c*16+u, t, h, w] = sum_{a,b} x[c, t, h+a-2, w+b-2] * filters[a*5+b, u, t, h, w]
//
// R3: float4-vectorized filter loads / output stores over w.
// Block = 128 threads: (w4 = tid&31 -> w = 4*w4..4*w4+3, ug = tid>>5 -> u = 4*ug..4*ug+3).
// Grid = 3200 (one block per (t,h) row). 48 accumulators/thread.

#define T_DIM 25
#define H_DIM 128
#define W_DIM 128
#define HW    (H_DIM * W_DIM)       // 16384
#define THW   (T_DIM * HW)          // 409600
#define C_IN  3
#define KH    5
#define KW    5
#define NK    (KH * KW)             // 25
#define UPSQ  16
#define UG    4                     // u per thread

__global__ __launch_bounds__(128, 6)
void duf_kernel(const float* __restrict__ x,
                const float* __restrict__ f,
                float* __restrict__ out)
{
    const int tid = threadIdx.x;
    const int w4  = tid & 31;            // float4 index over w: w0 = 4*w4
    const int ug  = tid >> 5;            // u group: u = 4*ug + j
    const int w0  = w4 << 2;
    const int h = blockIdx.x & (H_DIM - 1);
    const int t = blockIdx.x >> 7;

    // x patch tile: 3 channels x 5 rows x (128 + 4) cols, zero halo in w
    __shared__ float sx[C_IN][KH][W_DIM + 4];

    if (tid < 2) {
        #pragma unroll
        for (int c = 0; c < C_IN; c++)
            #pragma unroll
            for (int a = 0; a < KH; a++) {
                sx[c][a][tid] = 0.0f;
                sx[c][a][W_DIM + 2 + tid] = 0.0f;
            }
    }

    // stage x rows h-2..h+2 for all 3 channels (tid = w index here)
    #pragma unroll
    for (int c = 0; c < C_IN; c++) {
        #pragma unroll
        for (int a = 0; a < KH; a++) {
            const int hh = h + a - 2;
            float v = 0.0f;
            if (hh >= 0 && hh < H_DIM)
                v = __ldg(&x[c * THW + t * HW + hh * W_DIM + tid]);
            sx[c][a][tid + 2] = v;
        }
    }
    __syncthreads();

    const int rowbase = t * HW + h * W_DIM;                 // pixel base of this row
    // filter pointer for (k=0, u=4*ug, this row, w0)
    const float4* fp = (const float4*)(f + (size_t)(ug * UG) * THW + rowbase + w0);

    // acc[c][j][i] : c channel, j u-offset, i w-offset  -> 48 regs
    float4 acc[C_IN][UG];
    #pragma unroll
    for (int c = 0; c < C_IN; c++)
        #pragma unroll
        for (int j = 0; j < UG; j++)
            acc[c][j] = make_float4(0.f, 0.f, 0.f, 0.f);

    #pragma unroll 1
    for (int k = 0; k < NK; k++) {
        const int a = k / KW;
        const int b = k - a * KW;

        // 4 independent 512B-per-warp streaming loads in flight
        const float4* fk = fp + (size_t)k * (UPSQ * THW / 4);
        float4 fv0 = __ldg(fk);
        float4 fv1 = __ldg(fk + THW / 4);
        float4 fv2 = __ldg(fk + 2 * (THW / 4));
        float4 fv3 = __ldg(fk + 3 * (THW / 4));

        // patches for 4 consecutive w at this (a,b): sx[c][a][w0+b .. w0+b+3]
        float p[C_IN][4];
        #pragma unroll
        for (int c = 0; c < C_IN; c++)
            #pragma unroll
            for (int i = 0; i < 4; i++)
                p[c][i] = sx[c][a][w0 + b + i];

        #pragma unroll
        for (int c = 0; c < C_IN; c++) {
            acc[c][0].x = fmaf(p[c][0], fv0.x, acc[c][0].x);
            acc[c][0].y = fmaf(p[c][1], fv0.y, acc[c][0].y);
            acc[c][0].z = fmaf(p[c][2], fv0.z, acc[c][0].z);
            acc[c][0].w = fmaf(p[c][3], fv0.w, acc[c][0].w);
            acc[c][1].x = fmaf(p[c][0], fv1.x, acc[c][1].x);
            acc[c][1].y = fmaf(p[c][1], fv1.y, acc[c][1].y);
            acc[c][1].z = fmaf(p[c][2], fv1.z, acc[c][1].z);
            acc[c][1].w = fmaf(p[c][3], fv1.w, acc[c][1].w);
            acc[c][2].x = fmaf(p[c][0], fv2.x, acc[c][2].x);
            acc[c][2].y = fmaf(p[c][1], fv2.y, acc[c][2].y);
            acc[c][2].z = fmaf(p[c][2], fv2.z, acc[c][2].z);
            acc[c][2].w = fmaf(p[c][3], fv2.w, acc[c][2].w);
            acc[c][3].x = fmaf(p[c][0], fv3.x, acc[c][3].x);
            acc[c][3].y = fmaf(p[c][1], fv3.y, acc[c][3].y);
            acc[c][3].z = fmaf(p[c][2], fv3.z, acc[c][3].z);
            acc[c][3].w = fmaf(p[c][3], fv3.w, acc[c][3].w);
        }
    }

    // out[(c*16 + 4*ug + j)*THW + rowbase + w0], 512B/warp stores
    float4* op = (float4*)(out + (size_t)(ug * UG) * THW + rowbase + w0);
    #pragma unroll
    for (int c = 0; c < C_IN; c++)
        #pragma unroll
        for (int j = 0; j < UG; j++)
            op[((size_t)c * UPSQ + j) * (THW / 4)] = acc[c][j];
}

extern "C" void kernel_launch(void* const* d_in, const int* in_sizes, int n_in,
                              void* d_out, int out_size)
{
    const float* x = (const float*)d_in[0];
    const float* f = (const float*)d_in[1];
    float* out = (float*)d_out;

    dim3 grid(T_DIM * H_DIM);   // 3200 blocks: one per (t, h) row
    dim3 block(128);
    duf_kernel<<<grid, block>>>(x, f, out);
}